// round 11
// baseline (speedup 1.0000x reference)
#include <cuda_runtime.h>
#include <math.h>

// Problem constants
#define DIRS 2
#define BB   32
#define TT   512
#define DD   512
#define HH   512
#define G4   2048            // 4*H
#define TBM  16384           // T*B
#define NBLK 128             // persistent scan grid (1 block/SM, all co-resident)

static const size_t OUT_HN = (size_t)BB * TT * 2 * HH;   // 16777216
static const size_t OUT_CN = OUT_HN + 4ULL * BB * HH;    // 16842752

typedef unsigned long long ull;

// ---------------- scratch (static device globals; no allocation) ----------------
__device__ __align__(16) float g_xm[(size_t)TBM * 1024];
__device__ __align__(16) float g_xg[(size_t)DIRS * TBM * G4];
__device__ __align__(16) float g_y[(size_t)DIRS * TBM * HH];
__device__ __align__(16) float g_whhT[(size_t)2 * DIRS * HH * HH * 4]; // [layer][dir][hc][k][gate]
__device__ __align__(16) float g_hmT[2][DIRS * HH * BB];               // ping-pong [par][dir][k][b]
__device__ unsigned g_flags[DIRS * NBLK * 32];                         // flag per (dir,tile), 128B apart

// init-barrier state (atomic barrier used once per scan launch)
__device__ unsigned g_bar_count = 0;
__device__ unsigned g_bar_gen = 0;

// ---------------- f32x2 helpers ----------------
__device__ __forceinline__ ull pack2(float x, float y) {
    ull r;
    asm("mov.b64 %0, {%1, %2};" : "=l"(r) : "r"(__float_as_uint(x)), "r"(__float_as_uint(y)));
    return r;
}
__device__ __forceinline__ ull splat2(float x) {
    ull r; unsigned u = __float_as_uint(x);
    asm("mov.b64 %0, {%1, %1};" : "=l"(r) : "r"(u));
    return r;
}
__device__ __forceinline__ ull ffma2(ull a, ull b, ull c) {
    ull d;
    asm("fma.rn.f32x2 %0, %1, %2, %3;" : "=l"(d) : "l"(a), "l"(b), "l"(c));
    return d;
}
__device__ __forceinline__ float lo2(ull v) { return __uint_as_float((unsigned)(v & 0xffffffffu)); }
__device__ __forceinline__ float hi2(ull v) { return __uint_as_float((unsigned)(v >> 32)); }

// NaN-safe fast activations (MUFU-based)
__device__ __forceinline__ float fast_sigmoid(float x) {
    return __fdividef(1.0f, 1.0f + __expf(-x));
}
__device__ __forceinline__ float fast_tanh(float x) {
    return 1.0f - __fdividef(2.0f, 1.0f + __expf(2.0f * x));
}

// acquire/release flag ops (gpu scope)
__device__ __forceinline__ unsigned ld_acq(const unsigned* p) {
    unsigned v;
    asm volatile("ld.acquire.gpu.u32 %0, [%1];" : "=r"(v) : "l"(p) : "memory");
    return v;
}
__device__ __forceinline__ void st_rel(unsigned* p, unsigned v) {
    asm volatile("st.release.gpu.u32 [%0], %1;" :: "l"(p), "r"(v) : "memory");
}

// tf32 round-to-nearest conversion
__device__ __forceinline__ unsigned cvt_tf32(float f) {
    unsigned u;
    asm("cvt.rna.tf32.f32 %0, %1;" : "=r"(u) : "f"(f));
    return u;
}

// m16n8k8 tf32 MMA (row.col): D += A*B
__device__ __forceinline__ void mma_tf32(float* d, const unsigned* a, const unsigned* b) {
    asm volatile(
        "mma.sync.aligned.m16n8k8.row.col.f32.tf32.tf32.f32 "
        "{%0,%1,%2,%3}, {%4,%5,%6,%7}, {%8,%9}, {%0,%1,%2,%3};"
        : "+f"(d[0]), "+f"(d[1]), "+f"(d[2]), "+f"(d[3])
        : "r"(a[0]), "r"(a[1]), "r"(a[2]), "r"(a[3]), "r"(b[0]), "r"(b[1]));
}

// atomic sense-reversing grid barrier: used ONCE per scan launch (init only)
__device__ __forceinline__ void grid_barrier() {
    __syncthreads();
    if (threadIdx.x == 0) {
        __threadfence();
        volatile unsigned* genp = &g_bar_gen;
        unsigned old = *genp;
        unsigned t = atomicAdd(&g_bar_count, 1u);
        if (t == NBLK - 1) {
            g_bar_count = 0;
            __threadfence();
            g_bar_gen = old + 1;
        } else {
            while (*genp == old) {}
        }
        __threadfence();
    }
    __syncthreads();
}

// ---------------- prep kernels ----------------
__global__ void k_mask_in0(const float* __restrict__ x, const float* __restrict__ mask_x) {
    int gid = blockIdx.x * 256 + threadIdx.x;          // < 8388608
    int k = gid & 511; int b = (gid >> 9) & 31; int t = gid >> 14;
    g_xm[gid] = x[((size_t)b * TT + t) * DD + k] * mask_x[b * 512 + k];
}

__global__ void k_build_whhT(const float* __restrict__ w0, const float* __restrict__ w1) {
    int gid = blockIdx.x * 256 + threadIdx.x;          // < 4194304
    int g = gid & 3; int k = (gid >> 2) & 511; int hc = (gid >> 11) & 511;
    int dir = (gid >> 20) & 1; int layer = (gid >> 21) & 1;
    const float* w = layer ? w1 : w0;
    g_whhT[gid] = w[(size_t)dir * G4 * HH + (size_t)(g * HH + hc) * HH + k];
}

__global__ void k_build_in1(const float* __restrict__ mask_out) {
    int gid = blockIdx.x * 256 + threadIdx.x;          // < 16777216
    int j = gid & 1023; int b = (gid >> 10) & 31; int t = gid >> 15;
    int dir = j >> 9; int hc = j & 511;
    g_xm[gid] = g_y[(size_t)dir * TBM * HH + (size_t)(t * BB + b) * HH + hc] * mask_out[b * 1024 + j];
}

// ---------------- tf32 tensor-core input-projection GEMM ----------------
#define GS 20   // smem floats per row

__global__ void __launch_bounds__(256, 2) gemm_tf32(
    const float* __restrict__ A, const float* __restrict__ Wbase,
    const float* __restrict__ biasbase, float* __restrict__ Cbase, int K)
{
    __shared__ unsigned sA[2][128 * GS];
    __shared__ unsigned sB[2][128 * GS];
    const int dir = blockIdx.z;
    const float* W = Wbase + (size_t)dir * G4 * K;
    const float* bias = biasbase + dir * G4;
    float* C = Cbase + (size_t)dir * TBM * G4;

    const int tid = threadIdx.x;
    const int m0 = blockIdx.y * 128, n0 = blockIdx.x * 128;
    const int warp = tid >> 5, lane = tid & 31;
    const int wm0 = (warp & 3) * 32;
    const int wn0 = (warp >> 2) * 64;
    const int grp = lane >> 2, tig = lane & 3;

    const int ldr = tid >> 1;
    const int ldh = (tid & 1) * 8;
    const float* Ap = A + (size_t)(m0 + ldr) * K + ldh;
    const float* Wp = W + (size_t)(n0 + ldr) * K + ldh;
    unsigned* stA = &sA[0][ldr * GS + ldh];
    unsigned* stB = &sB[0][ldr * GS + ldh];
    const int bufstep = 128 * GS;

    float acc[2][8][4];
#pragma unroll
    for (int i = 0; i < 2; i++)
#pragma unroll
        for (int j = 0; j < 8; j++)
#pragma unroll
            for (int q = 0; q < 4; q++) acc[i][j][q] = 0.f;

    float bsv[8][2];
#pragma unroll
    for (int nt = 0; nt < 8; nt++) {
        int c = n0 + wn0 + nt * 8 + tig * 2;
        bsv[nt][0] = bias[c]; bsv[nt][1] = bias[c + 1];
    }

    {
        float4 a0 = *(const float4*)(Ap), a1 = *(const float4*)(Ap + 4);
        float4 w0 = *(const float4*)(Wp), w1 = *(const float4*)(Wp + 4);
        stA[0] = cvt_tf32(a0.x); stA[1] = cvt_tf32(a0.y); stA[2] = cvt_tf32(a0.z); stA[3] = cvt_tf32(a0.w);
        stA[4] = cvt_tf32(a1.x); stA[5] = cvt_tf32(a1.y); stA[6] = cvt_tf32(a1.z); stA[7] = cvt_tf32(a1.w);
        stB[0] = cvt_tf32(w0.x); stB[1] = cvt_tf32(w0.y); stB[2] = cvt_tf32(w0.z); stB[3] = cvt_tf32(w0.w);
        stB[4] = cvt_tf32(w1.x); stB[5] = cvt_tf32(w1.y); stB[6] = cvt_tf32(w1.z); stB[7] = cvt_tf32(w1.w);
    }
    __syncthreads();

    const int KT = K >> 4;
    for (int kt = 0; kt < KT; kt++) {
        const int buf = kt & 1;
        float4 na0, na1, nw0, nw1;
        const bool more = (kt + 1 < KT);
        if (more) {
            const float* ap = Ap + (kt + 1) * 16;
            const float* wp = Wp + (kt + 1) * 16;
            na0 = *(const float4*)(ap); na1 = *(const float4*)(ap + 4);
            nw0 = *(const float4*)(wp); nw1 = *(const float4*)(wp + 4);
        }

        const unsigned* bA = &sA[0][buf * bufstep];
        const unsigned* bW = &sB[0][buf * bufstep];
#pragma unroll
        for (int ks = 0; ks < 16; ks += 8) {
            unsigned afr[2][4];
#pragma unroll
            for (int mt = 0; mt < 2; mt++) {
                int ra = wm0 + mt * 16 + grp;
                afr[mt][0] = bA[ra * GS + ks + tig];
                afr[mt][1] = bA[(ra + 8) * GS + ks + tig];
                afr[mt][2] = bA[ra * GS + ks + tig + 4];
                afr[mt][3] = bA[(ra + 8) * GS + ks + tig + 4];
            }
#pragma unroll
            for (int nt = 0; nt < 8; nt++) {
                int rb = wn0 + nt * 8 + grp;
                unsigned bfr[2];
                bfr[0] = bW[rb * GS + ks + tig];
                bfr[1] = bW[rb * GS + ks + tig + 4];
                mma_tf32(acc[0][nt], afr[0], bfr);
                mma_tf32(acc[1][nt], afr[1], bfr);
            }
        }

        if (more) {
            unsigned* dA = stA + (buf ^ 1) * bufstep;
            unsigned* dB = stB + (buf ^ 1) * bufstep;
            dA[0] = cvt_tf32(na0.x); dA[1] = cvt_tf32(na0.y); dA[2] = cvt_tf32(na0.z); dA[3] = cvt_tf32(na0.w);
            dA[4] = cvt_tf32(na1.x); dA[5] = cvt_tf32(na1.y); dA[6] = cvt_tf32(na1.z); dA[7] = cvt_tf32(na1.w);
            dB[0] = cvt_tf32(nw0.x); dB[1] = cvt_tf32(nw0.y); dB[2] = cvt_tf32(nw0.z); dB[3] = cvt_tf32(nw0.w);
            dB[4] = cvt_tf32(nw1.x); dB[5] = cvt_tf32(nw1.y); dB[6] = cvt_tf32(nw1.z); dB[7] = cvt_tf32(nw1.w);
            __syncthreads();
        }
    }

#pragma unroll
    for (int mt = 0; mt < 2; mt++) {
        int r = m0 + wm0 + mt * 16 + grp;
#pragma unroll
        for (int nt = 0; nt < 8; nt++) {
            int c = n0 + wn0 + nt * 8 + tig * 2;
            float2 v0 = make_float2(acc[mt][nt][0] + bsv[nt][0], acc[mt][nt][1] + bsv[nt][1]);
            float2 v1 = make_float2(acc[mt][nt][2] + bsv[nt][0], acc[mt][nt][3] + bsv[nt][1]);
            *(float2*)&C[(size_t)r * G4 + c] = v0;
            *(float2*)&C[(size_t)(r + 8) * G4 + c] = v1;
        }
    }
}

// ---------------- dual-direction interleaved persistent scan ----------------
// 128 blocks; block = hc tile of 4 (jt4 = bx), handles BOTH directions per step:
//   phase d0: wait d0 flags -> stage h0 -> GEMM -> reduce -> pointwise -> release d0
//   phase d1: (d0 compute hid the d1 flag/h propagation) same for dir 1.
// Thread (kc32 x [hcp2 x bq4]): tile 2hc x 4g x 8b over 16 k. In-block SMEM reduce.
#define WROW 546          // float4 per weight row (512 + 17*2 skew pad): col' = col + (col>>4)
#define HCHUNK 129        // float4 per 16-k h chunk (128 + 1 pad: conflict-free)
#define RED_STRIDE 33     // float4 per (kc,hc) reduction row (32 + pad)
#define SM_W  (8 * WROW)              // 4368 f4
#define SM_H  (32 * HCHUNK)           // 4128 f4
#define SM_R  (128 * RED_STRIDE)      // 4224 f4
#define SCAN_SMEM ((SM_W + SM_H + SM_R) * 16)   // 203520 B

__global__ void __launch_bounds__(256, 1) lstm_scan(int layer, float* __restrict__ out,
                                                    const float* __restrict__ mask_h) {
    extern __shared__ __align__(16) float4 smem4[];
    float4* sw4  = smem4;             // weights [dir2*hc4][skewed 512]
    float4* H4   = smem4 + SM_W;      // staged h, one dir at a time
    float4* red4 = H4 + SM_H;         // kc partials

    const int jt4 = blockIdx.x;       // hc tile of 4
    const int tid = threadIdx.x;

    const int kc  = tid >> 3;         // 0..31 : 16-k chunk
    const int sub = tid & 7;          // lane within kc group
    const int hcp = (tid >> 2) & 1;   // hc pair within tile (2 hc)
    const int bq  = tid & 3;          // 8-b group

    // load weight slices for BOTH dirs into skewed SMEM once
    {
        const float* whh = g_whhT + (size_t)layer * 2097152;   // layer slab (2*512*512*4)
        for (int idx = tid; idx < 8 * 512; idx += 256) {
            int r = idx >> 9;          // 0..7 : dir*4 + hc_local
            int c = idx & 511;         // k (float4 of 4 gates)
            int d = r >> 2, hcl = r & 3;
            sw4[r * WROW + c + (c >> 4)] =
                ((const float4*)whh)[((size_t)d * 512 + jt4 * 4 + hcl) * 512 + c];
        }
    }

    // pointwise identity (tid < 128)
    const int hc_local = tid >> 5;    // 0..7 (valid 0..3 for tid<128)
    const int b2 = tid & 31;
    const int hcg = jt4 * 4 + (hc_local & 3);
    float mh = 0.f;
    if (tid < 128) mh = mask_h[(size_t)layer * 16384 + b2 * 512 + hcg];
    float h_r[2] = {0.f, 0.f}, c_r[2] = {0.f, 0.f};

    // init: h(-1)=0 in par=1 buffer for own rows, both dirs; reset flags
    if (tid < 128) {
        g_hmT[1][0 * 16384 + hcg * 32 + b2] = 0.f;
        g_hmT[1][1 * 16384 + hcg * 32 + b2] = 0.f;
    }
    if (tid == 0) {
        *(volatile unsigned*)&g_flags[(0 * NBLK + jt4) * 32] = 0u;
        *(volatile unsigned*)&g_flags[(1 * NBLK + jt4) * 32] = 0u;
    }
    grid_barrier();

    const float4* wr0base = sw4 + (hcp * 2) * WROW + kc * 17;   // + d*4*WROW per phase
    const float4* hrow = H4 + kc * HCHUNK + bq * 2;

    for (int s = 0; s < TT; s++) {
#pragma unroll
        for (int d = 0; d < 2; d++) {
            const int t = d ? (TT - 1 - s) : s;

            // prefetch xg gates (hidden under stage+GEMM)
            float xi = 0.f, xf = 0.f, xg_ = 0.f, xo = 0.f;
            if (tid < 128) {
                const float* xgb = g_xg + ((size_t)d * TBM + (size_t)t * BB + b2) * G4 + hcg;
                xi = __ldcg(xgb); xf = __ldcg(xgb + HH);
                xg_ = __ldcg(xgb + 2 * HH); xo = __ldcg(xgb + 3 * HH);
            }

            // wait for the 4 producers of this kc chunk (lanes sub<4, tight spin)
            if (s > 0 && sub < 4) {
                const unsigned* pf = g_flags + (d * NBLK + kc * 4 + sub) * 32;
                unsigned tgt = (unsigned)s;
                while (ld_acq(pf) < tgt) {}
            }
            __syncwarp();

            // stage own kc chunk of h(s-1) for dir d
            const float4* hb = (const float4*)(g_hmT[(s + 1) & 1]) + d * 4096 + kc * 128;
#pragma unroll
            for (int i = 0; i < 16; i++)
                H4[kc * HCHUNK + i * 8 + sub] = __ldcg(hb + i * 8 + sub);
            __syncwarp();

            // recurrent GEMM: 2hc x 4g x 8b over 16 k
            const float4* wr0 = wr0base + d * 4 * WROW;
            const float4* wr1 = wr0 + WROW;
            ull a0[8][2], a1[8][2];
#pragma unroll
            for (int i = 0; i < 8; i++) { a0[i][0] = 0; a0[i][1] = 0; a1[i][0] = 0; a1[i][1] = 0; }

#pragma unroll 8
            for (int kk = 0; kk < 16; kk++) {
                ulonglong2 w0 = *(const ulonglong2*)(wr0 + kk);   // .x = gates i,f ; .y = g,o
                ulonglong2 w1 = *(const ulonglong2*)(wr1 + kk);
                float4 hA = hrow[kk * 8];
                float4 hB = hrow[kk * 8 + 1];
                float hv[8] = {hA.x, hA.y, hA.z, hA.w, hB.x, hB.y, hB.z, hB.w};
#pragma unroll
                for (int ib = 0; ib < 8; ib++) {
                    ull h2 = splat2(hv[ib]);
                    a0[ib][0] = ffma2(h2, w0.x, a0[ib][0]);
                    a0[ib][1] = ffma2(h2, w0.y, a0[ib][1]);
                    a1[ib][0] = ffma2(h2, w1.x, a1[ib][0]);
                    a1[ib][1] = ffma2(h2, w1.y, a1[ib][1]);
                }
            }

            // partials -> reduction buffer: rows (kc*4 + hcp*2 + {0,1})
            {
                float4* r0 = red4 + (size_t)(kc * 4 + hcp * 2) * RED_STRIDE + bq * 8;
                float4* r1 = r0 + RED_STRIDE;
#pragma unroll
                for (int ib = 0; ib < 8; ib++) {
                    r0[ib] = make_float4(lo2(a0[ib][0]), hi2(a0[ib][0]), lo2(a0[ib][1]), hi2(a0[ib][1]));
                    r1[ib] = make_float4(lo2(a1[ib][0]), hi2(a1[ib][0]), lo2(a1[ib][1]), hi2(a1[ib][1]));
                }
            }
            __syncthreads();

            // reduce over 32 kc + pointwise LSTM (tid < 128)
            if (tid < 128) {
                float gi = xi, gf = xf, gg = xg_, go = xo;
#pragma unroll
                for (int k32 = 0; k32 < 32; k32++) {
                    float4 v = red4[(size_t)(k32 * 4 + hc_local) * RED_STRIDE + b2];
                    gi += v.x; gf += v.y; gg += v.z; go += v.w;
                }
                c_r[d] = fast_sigmoid(gf) * c_r[d] + fast_sigmoid(gi) * fast_tanh(gg);
                h_r[d] = fast_sigmoid(go) * fast_tanh(c_r[d]);
                __stcg(&g_hmT[s & 1][d * 16384 + hcg * 32 + b2], h_r[d] * mh);
            }
            __syncthreads();
            if (tid == 0) st_rel(g_flags + (d * NBLK + jt4) * 32, (unsigned)(s + 1));

            // off-path output stores after the signal
            if (tid < 128) {
                if (layer == 0)
                    g_y[(size_t)d * TBM * HH + ((size_t)t * BB + b2) * HH + hcg] = h_r[d];
                else
                    out[((size_t)b2 * TT + t) * (2 * HH) + d * HH + hcg] = h_r[d];
            }
        }
    }

    // final hn / cn: [layer*2+dir][b][h]
    if (tid < 128) {
#pragma unroll
        for (int d = 0; d < 2; d++) {
            out[OUT_HN + (size_t)layer * 32768 + d * 16384 + b2 * 512 + hcg] = h_r[d];
            out[OUT_CN + (size_t)layer * 32768 + d * 16384 + b2 * 512 + hcg] = c_r[d];
        }
    }
}

// ---------------- launcher ----------------
extern "C" void kernel_launch(void* const* d_in, const int* in_sizes, int n_in,
                              void* d_out, int out_size) {
    (void)in_sizes; (void)n_in; (void)out_size;
    const float* x       = (const float*)d_in[0];
    const float* mask_x  = (const float*)d_in[1];
    const float* mask_out= (const float*)d_in[2];
    const float* mask_h  = (const float*)d_in[3];
    const float* w_ih_l0 = (const float*)d_in[4];
    const float* w_hh_l0 = (const float*)d_in[5];
    const float* b_l0    = (const float*)d_in[6];
    const float* w_ih_l1 = (const float*)d_in[7];
    const float* w_hh_l1 = (const float*)d_in[8];
    const float* b_l1    = (const float*)d_in[9];
    float* out = (float*)d_out;

    float *p_xm = nullptr, *p_xg = nullptr;
    cudaGetSymbolAddress((void**)&p_xm, g_xm);
    cudaGetSymbolAddress((void**)&p_xg, g_xg);

    cudaFuncSetAttribute(lstm_scan, cudaFuncAttributeMaxDynamicSharedMemorySize, SCAN_SMEM);

    // our launches #1..#3 before scan0 (#4) -> process #6 = scan0 under ncu -s 5
    k_mask_in0<<<8388608 / 256, 256>>>(x, mask_x);                              // #1
    gemm_tf32<<<dim3(16, 128, 2), 256>>>(p_xm, w_ih_l0, b_l0, p_xg, DD);        // #2
    k_build_whhT<<<4194304 / 256, 256>>>(w_hh_l0, w_hh_l1);                     // #3

    lstm_scan<<<NBLK, 256, SCAN_SMEM>>>(0, out, mask_h);                        // #4

    k_build_in1<<<16777216 / 256, 256>>>(mask_out);                             // #5
    gemm_tf32<<<dim3(16, 128, 2), 256>>>(p_xm, w_ih_l1, b_l1, p_xg, 2 * HH);    // #6
    lstm_scan<<<NBLK, 256, SCAN_SMEM>>>(1, out, mask_h);                        // #7
}

// round 12
// speedup vs baseline: 1.5403x; 1.5403x over previous
#include <cuda_runtime.h>
#include <math.h>

// Problem constants
#define DIRS 2
#define BB   32
#define TT   512
#define DD   512
#define HH   512
#define G4   2048            // 4*H
#define TBM  16384           // T*B
#define NBLK 128             // persistent scan grid (1 block/SM, all co-resident)

static const size_t OUT_HN = (size_t)BB * TT * 2 * HH;   // 16777216
static const size_t OUT_CN = OUT_HN + 4ULL * BB * HH;    // 16842752

typedef unsigned long long ull;

// ---------------- scratch (static device globals; no allocation) ----------------
__device__ __align__(16) float g_xm[(size_t)TBM * 1024];
__device__ __align__(16) float g_xg[(size_t)DIRS * TBM * G4];
__device__ __align__(16) float g_y[(size_t)DIRS * HH * TBM];           // [dir][hc][t][b]  (transposed layout)
__device__ __align__(16) float g_whhT[(size_t)2 * DIRS * HH * HH * 4]; // [layer][dir][hc][k][gate]
__device__ __align__(16) float g_hmT[2][DIRS * HH * BB];               // ping-pong [par][dir][k][b]
__device__ unsigned g_flags[DIRS * 64 * 32];                           // flag per (dir,jt), 128B apart

// init-barrier state (atomic barrier used once per scan launch)
__device__ unsigned g_bar_count = 0;
__device__ unsigned g_bar_gen = 0;

// ---------------- f32x2 helpers ----------------
__device__ __forceinline__ ull pack2(float x, float y) {
    ull r;
    asm("mov.b64 %0, {%1, %2};" : "=l"(r) : "r"(__float_as_uint(x)), "r"(__float_as_uint(y)));
    return r;
}
__device__ __forceinline__ ull splat2(float x) {
    ull r; unsigned u = __float_as_uint(x);
    asm("mov.b64 %0, {%1, %1};" : "=l"(r) : "r"(u));
    return r;
}
__device__ __forceinline__ ull ffma2(ull a, ull b, ull c) {
    ull d;
    asm("fma.rn.f32x2 %0, %1, %2, %3;" : "=l"(d) : "l"(a), "l"(b), "l"(c));
    return d;
}
__device__ __forceinline__ float lo2(ull v) { return __uint_as_float((unsigned)(v & 0xffffffffu)); }
__device__ __forceinline__ float hi2(ull v) { return __uint_as_float((unsigned)(v >> 32)); }

// NaN-safe fast activations (MUFU-based)
__device__ __forceinline__ float fast_sigmoid(float x) {
    return __fdividef(1.0f, 1.0f + __expf(-x));
}
__device__ __forceinline__ float fast_tanh(float x) {
    return 1.0f - __fdividef(2.0f, 1.0f + __expf(2.0f * x));
}

// acquire/release flag ops (gpu scope)
__device__ __forceinline__ unsigned ld_acq(const unsigned* p) {
    unsigned v;
    asm volatile("ld.acquire.gpu.u32 %0, [%1];" : "=r"(v) : "l"(p) : "memory");
    return v;
}
__device__ __forceinline__ void st_rel(unsigned* p, unsigned v) {
    asm volatile("st.release.gpu.u32 [%0], %1;" :: "l"(p), "r"(v) : "memory");
}

// tf32 round-to-nearest conversion
__device__ __forceinline__ unsigned cvt_tf32(float f) {
    unsigned u;
    asm("cvt.rna.tf32.f32 %0, %1;" : "=r"(u) : "f"(f));
    return u;
}

// m16n8k8 tf32 MMA (row.col): D += A*B
__device__ __forceinline__ void mma_tf32(float* d, const unsigned* a, const unsigned* b) {
    asm volatile(
        "mma.sync.aligned.m16n8k8.row.col.f32.tf32.tf32.f32 "
        "{%0,%1,%2,%3}, {%4,%5,%6,%7}, {%8,%9}, {%0,%1,%2,%3};"
        : "+f"(d[0]), "+f"(d[1]), "+f"(d[2]), "+f"(d[3])
        : "r"(a[0]), "r"(a[1]), "r"(a[2]), "r"(a[3]), "r"(b[0]), "r"(b[1]));
}

// atomic sense-reversing grid barrier: used ONCE per scan launch (init only)
__device__ __forceinline__ void grid_barrier() {
    __syncthreads();
    if (threadIdx.x == 0) {
        __threadfence();
        volatile unsigned* genp = &g_bar_gen;
        unsigned old = *genp;
        unsigned t = atomicAdd(&g_bar_count, 1u);
        if (t == NBLK - 1) {
            g_bar_count = 0;
            __threadfence();
            g_bar_gen = old + 1;
        } else {
            while (*genp == old) {}
        }
        __threadfence();
    }
    __syncthreads();
}

// ---------------- prep kernels ----------------
__global__ void k_mask_in0(const float* __restrict__ x, const float* __restrict__ mask_x) {
    int gid = blockIdx.x * 256 + threadIdx.x;          // < 8388608
    int k = gid & 511; int b = (gid >> 9) & 31; int t = gid >> 14;
    g_xm[gid] = x[((size_t)b * TT + t) * DD + k] * mask_x[b * 512 + k];
}

__global__ void k_build_whhT(const float* __restrict__ w0, const float* __restrict__ w1) {
    int gid = blockIdx.x * 256 + threadIdx.x;          // < 4194304
    int g = gid & 3; int k = (gid >> 2) & 511; int hc = (gid >> 11) & 511;
    int dir = (gid >> 20) & 1; int layer = (gid >> 21) & 1;
    const float* w = layer ? w1 : w0;
    g_whhT[gid] = w[(size_t)dir * G4 * HH + (size_t)(g * HH + hc) * HH + k];
}

// tiled transpose: g_xm[(t*32+b)*1024 + jg] = g_y[jg][t][b] * mask_out[b][jg]
__global__ void k_build_in1(const float* __restrict__ mask_out) {
    __shared__ float tile[32][33];
    const int t = blockIdx.x;          // 0..511
    const int jt = blockIdx.y;         // 0..31
    const int wid = threadIdx.x >> 5, lane = threadIdx.x & 31;
#pragma unroll
    for (int i = 0; i < 4; i++) {
        int r = i * 8 + wid;           // j offset within tile
        tile[r][lane] = g_y[(size_t)(jt * 32 + r) * TBM + t * 32 + lane];
    }
    __syncthreads();
#pragma unroll
    for (int i = 0; i < 4; i++) {
        int b = i * 8 + wid;
        int jg = jt * 32 + lane;
        g_xm[((size_t)t * 32 + b) * 1024 + jg] = tile[lane][b] * mask_out[b * 1024 + jg];
    }
}

// tiled transpose: out[b][t][jg] = g_y[jg][t][b]   (layer-1 outputs)
__global__ void k_out_tr(float* __restrict__ out) {
    __shared__ float tile[32][33];
    const int t = blockIdx.x;
    const int jt = blockIdx.y;
    const int wid = threadIdx.x >> 5, lane = threadIdx.x & 31;
#pragma unroll
    for (int i = 0; i < 4; i++) {
        int r = i * 8 + wid;
        tile[r][lane] = g_y[(size_t)(jt * 32 + r) * TBM + t * 32 + lane];
    }
    __syncthreads();
#pragma unroll
    for (int i = 0; i < 4; i++) {
        int b = i * 8 + wid;
        out[((size_t)b * TT + t) * 1024 + jt * 32 + lane] = tile[lane][b];
    }
}

// ---------------- tf32 tensor-core input-projection GEMM ----------------
#define GS 20   // smem floats per row

__global__ void __launch_bounds__(256, 2) gemm_tf32(
    const float* __restrict__ A, const float* __restrict__ Wbase,
    const float* __restrict__ biasbase, float* __restrict__ Cbase, int K)
{
    __shared__ unsigned sA[2][128 * GS];
    __shared__ unsigned sB[2][128 * GS];
    const int dir = blockIdx.z;
    const float* W = Wbase + (size_t)dir * G4 * K;
    const float* bias = biasbase + dir * G4;
    float* C = Cbase + (size_t)dir * TBM * G4;

    const int tid = threadIdx.x;
    const int m0 = blockIdx.y * 128, n0 = blockIdx.x * 128;
    const int warp = tid >> 5, lane = tid & 31;
    const int wm0 = (warp & 3) * 32;
    const int wn0 = (warp >> 2) * 64;
    const int grp = lane >> 2, tig = lane & 3;

    const int ldr = tid >> 1;
    const int ldh = (tid & 1) * 8;
    const float* Ap = A + (size_t)(m0 + ldr) * K + ldh;
    const float* Wp = W + (size_t)(n0 + ldr) * K + ldh;
    unsigned* stA = &sA[0][ldr * GS + ldh];
    unsigned* stB = &sB[0][ldr * GS + ldh];
    const int bufstep = 128 * GS;

    float acc[2][8][4];
#pragma unroll
    for (int i = 0; i < 2; i++)
#pragma unroll
        for (int j = 0; j < 8; j++)
#pragma unroll
            for (int q = 0; q < 4; q++) acc[i][j][q] = 0.f;

    float bsv[8][2];
#pragma unroll
    for (int nt = 0; nt < 8; nt++) {
        int c = n0 + wn0 + nt * 8 + tig * 2;
        bsv[nt][0] = bias[c]; bsv[nt][1] = bias[c + 1];
    }

    {
        float4 a0 = *(const float4*)(Ap), a1 = *(const float4*)(Ap + 4);
        float4 w0 = *(const float4*)(Wp), w1 = *(const float4*)(Wp + 4);
        stA[0] = cvt_tf32(a0.x); stA[1] = cvt_tf32(a0.y); stA[2] = cvt_tf32(a0.z); stA[3] = cvt_tf32(a0.w);
        stA[4] = cvt_tf32(a1.x); stA[5] = cvt_tf32(a1.y); stA[6] = cvt_tf32(a1.z); stA[7] = cvt_tf32(a1.w);
        stB[0] = cvt_tf32(w0.x); stB[1] = cvt_tf32(w0.y); stB[2] = cvt_tf32(w0.z); stB[3] = cvt_tf32(w0.w);
        stB[4] = cvt_tf32(w1.x); stB[5] = cvt_tf32(w1.y); stB[6] = cvt_tf32(w1.z); stB[7] = cvt_tf32(w1.w);
    }
    __syncthreads();

    const int KT = K >> 4;
    for (int kt = 0; kt < KT; kt++) {
        const int buf = kt & 1;
        float4 na0, na1, nw0, nw1;
        const bool more = (kt + 1 < KT);
        if (more) {
            const float* ap = Ap + (kt + 1) * 16;
            const float* wp = Wp + (kt + 1) * 16;
            na0 = *(const float4*)(ap); na1 = *(const float4*)(ap + 4);
            nw0 = *(const float4*)(wp); nw1 = *(const float4*)(wp + 4);
        }

        const unsigned* bA = &sA[0][buf * bufstep];
        const unsigned* bW = &sB[0][buf * bufstep];
#pragma unroll
        for (int ks = 0; ks < 16; ks += 8) {
            unsigned afr[2][4];
#pragma unroll
            for (int mt = 0; mt < 2; mt++) {
                int ra = wm0 + mt * 16 + grp;
                afr[mt][0] = bA[ra * GS + ks + tig];
                afr[mt][1] = bA[(ra + 8) * GS + ks + tig];
                afr[mt][2] = bA[ra * GS + ks + tig + 4];
                afr[mt][3] = bA[(ra + 8) * GS + ks + tig + 4];
            }
#pragma unroll
            for (int nt = 0; nt < 8; nt++) {
                int rb = wn0 + nt * 8 + grp;
                unsigned bfr[2];
                bfr[0] = bW[rb * GS + ks + tig];
                bfr[1] = bW[rb * GS + ks + tig + 4];
                mma_tf32(acc[0][nt], afr[0], bfr);
                mma_tf32(acc[1][nt], afr[1], bfr);
            }
        }

        if (more) {
            unsigned* dA = stA + (buf ^ 1) * bufstep;
            unsigned* dB = stB + (buf ^ 1) * bufstep;
            dA[0] = cvt_tf32(na0.x); dA[1] = cvt_tf32(na0.y); dA[2] = cvt_tf32(na0.z); dA[3] = cvt_tf32(na0.w);
            dA[4] = cvt_tf32(na1.x); dA[5] = cvt_tf32(na1.y); dA[6] = cvt_tf32(na1.z); dA[7] = cvt_tf32(na1.w);
            dB[0] = cvt_tf32(nw0.x); dB[1] = cvt_tf32(nw0.y); dB[2] = cvt_tf32(nw0.z); dB[3] = cvt_tf32(nw0.w);
            dB[4] = cvt_tf32(nw1.x); dB[5] = cvt_tf32(nw1.y); dB[6] = cvt_tf32(nw1.z); dB[7] = cvt_tf32(nw1.w);
            __syncthreads();
        }
    }

#pragma unroll
    for (int mt = 0; mt < 2; mt++) {
        int r = m0 + wm0 + mt * 16 + grp;
#pragma unroll
        for (int nt = 0; nt < 8; nt++) {
            int c = n0 + wn0 + nt * 8 + tig * 2;
            float2 v0 = make_float2(acc[mt][nt][0] + bsv[nt][0], acc[mt][nt][1] + bsv[nt][1]);
            float2 v1 = make_float2(acc[mt][nt][2] + bsv[nt][0], acc[mt][nt][3] + bsv[nt][1]);
            *(float2*)&C[(size_t)r * G4 + c] = v0;
            *(float2*)&C[(size_t)(r + 8) * G4 + c] = v1;
        }
    }
}

// ---------------- full-K persistent scan: warp-per-hc, pointwise fused in-thread ----------------
// 128 blocks: (dir = bx>>6, jt = bx&63). Block owns hc tile [jt*8, jt*8+8), warp w = hc jt*8+w.
// Thread (hc=wid, b=lane): all 4 gates over full K=512 in registers -> no reduction phase.
// Weights (64KB, ulonglong2 (i,f)|(g,o) per (hc,k)) + staged h (64KB, [k][b]) in SMEM.
// Warp w stages k-chunk [w*64,w*64+64) after polling its 8 producers (overlap with stragglers).
#define SCAN_SMEM (65536 + 65536)   // weights + h stage

__global__ void __launch_bounds__(256, 1) lstm_scan(int layer, float* __restrict__ out,
                                                    const float* __restrict__ mask_h) {
    extern __shared__ __align__(16) char smem[];
    ull* sw = (ull*)smem;                         // [8 hc][512 k][2]  (i,f),(g,o)
    float* sh = (float*)(smem + 65536);           // [512 k][32 b]

    const int bx = blockIdx.x;
    const int tid = threadIdx.x;
    const int dirb = bx >> 6;
    const int jt = bx & 63;
    const int wid = tid >> 5;                     // hc within tile
    const int lane = tid & 31;                    // b
    const int hcg = jt * 8 + wid;

    // load weight slice once: direct copy of g_whhT rows (float4 (i,f,g,o) == ulonglong2)
    {
        const float4* whhT4 = (const float4*)g_whhT;
        const size_t base = ((size_t)(layer * 2 + dirb) * 512 + jt * 8) * 512;
        float4* sw4 = (float4*)sw;
        for (int idx = tid; idx < 4096; idx += 256)
            sw4[idx] = whhT4[base + idx];
    }

    const float mh = mask_h[(size_t)layer * 16384 + lane * 512 + hcg];
    float h_r = 0.f, c_r = 0.f;

    // init h(-1) = 0 and reset own flag; one atomic barrier publishes everything
    g_hmT[1][dirb * 16384 + hcg * 32 + lane] = 0.f;
    if (tid == 0) *(volatile unsigned*)&g_flags[(dirb * 64 + jt) * 32] = 0u;
    grid_barrier();

    unsigned* myflag = g_flags + (dirb * 64 + jt) * 32;
    const ull* wrow = sw + (size_t)wid * 1024;    // 512 k * 2 ull
    float* yrow = g_y + ((size_t)dirb * 512 + hcg) * TBM;

    for (int s = 0; s < TT; s++) {
        const int t = dirb ? (TT - 1 - s) : s;

        // prefetch xg gates (DRAM latency hidden under wait+GEMM)
        const float* xgb = g_xg + ((size_t)dirb * TBM + (size_t)t * BB + lane) * G4 + hcg;
        float xi = __ldcg(xgb);
        float xf = __ldcg(xgb + HH);
        float xg_ = __ldcg(xgb + 2 * HH);
        float xo = __ldcg(xgb + 3 * HH);

        // wait for the 8 producers of this warp's k-chunk (lanes 0..7 poll, tight spin)
        if (s > 0 && lane < 8) {
            const unsigned* pf = g_flags + (dirb * 64 + wid * 8 + lane) * 32;
            unsigned tgt = (unsigned)s;
            while (ld_acq(pf) < tgt) {}
        }
        __syncwarp();

        // stage own 64-k chunk of h(s-1): 512 float4, 16 per lane, coalesced
        {
            const float4* hb = (const float4*)(g_hmT[(s + 1) & 1]) + dirb * 4096 + wid * 512;
            float4* sh4 = (float4*)sh + wid * 512;
#pragma unroll
            for (int i = 0; i < 16; i++)
                sh4[i * 32 + lane] = __ldcg(hb + i * 32 + lane);
        }
        __syncthreads();   // all chunks staged

        // full-K GEMM: 4 gates for (hcg, b=lane)
        ull aif = 0, ago = 0;
        const float* hcol = sh + lane;
#pragma unroll 8
        for (int k = 0; k < 512; k++) {
            ull wif = wrow[k * 2];
            ull wgo = wrow[k * 2 + 1];
            ull h2 = splat2(hcol[k * 32]);
            aif = ffma2(h2, wif, aif);
            ago = ffma2(h2, wgo, ago);
        }

        // pointwise LSTM in-register
        float gi = lo2(aif) + xi;
        float gf = hi2(aif) + xf;
        float gg = lo2(ago) + xg_;
        float go = hi2(ago) + xo;
        c_r = fast_sigmoid(gf) * c_r + fast_sigmoid(gi) * fast_tanh(gg);
        h_r = fast_sigmoid(go) * fast_tanh(c_r);

        // critical-path store (coalesced 128B/warp), then block-wide release
        __stcg(&g_hmT[s & 1][dirb * 16384 + hcg * 32 + lane], h_r * mh);
        __syncthreads();
        if (tid == 0) st_rel(myflag, (unsigned)(s + 1));

        // off-path coalesced y store: g_y[dir][hc][t][b] (both layers)
        yrow[(size_t)t * BB + lane] = h_r;
    }

    // final hn / cn from registers: [layer*2+dir][b][h]
    out[OUT_HN + (size_t)layer * 32768 + dirb * 16384 + lane * 512 + hcg] = h_r;
    out[OUT_CN + (size_t)layer * 32768 + dirb * 16384 + lane * 512 + hcg] = c_r;
}

// ---------------- launcher ----------------
extern "C" void kernel_launch(void* const* d_in, const int* in_sizes, int n_in,
                              void* d_out, int out_size) {
    (void)in_sizes; (void)n_in; (void)out_size;
    const float* x       = (const float*)d_in[0];
    const float* mask_x  = (const float*)d_in[1];
    const float* mask_out= (const float*)d_in[2];
    const float* mask_h  = (const float*)d_in[3];
    const float* w_ih_l0 = (const float*)d_in[4];
    const float* w_hh_l0 = (const float*)d_in[5];
    const float* b_l0    = (const float*)d_in[6];
    const float* w_ih_l1 = (const float*)d_in[7];
    const float* w_hh_l1 = (const float*)d_in[8];
    const float* b_l1    = (const float*)d_in[9];
    float* out = (float*)d_out;

    float *p_xm = nullptr, *p_xg = nullptr;
    cudaGetSymbolAddress((void**)&p_xm, g_xm);
    cudaGetSymbolAddress((void**)&p_xg, g_xg);

    cudaFuncSetAttribute(lstm_scan, cudaFuncAttributeMaxDynamicSharedMemorySize, SCAN_SMEM);

    // our launches #1..#3 before scan0 (#4) -> process #6 = scan0 under ncu -s 5
    k_mask_in0<<<8388608 / 256, 256>>>(x, mask_x);                              // #1
    gemm_tf32<<<dim3(16, 128, 2), 256>>>(p_xm, w_ih_l0, b_l0, p_xg, DD);        // #2
    k_build_whhT<<<4194304 / 256, 256>>>(w_hh_l0, w_hh_l1);                     // #3

    lstm_scan<<<NBLK, 256, SCAN_SMEM>>>(0, out, mask_h);                        // #4

    k_build_in1<<<dim3(512, 32), 256>>>(mask_out);                              // #5
    gemm_tf32<<<dim3(16, 128, 2), 256>>>(p_xm, w_ih_l1, b_l1, p_xg, 2 * HH);    // #6
    lstm_scan<<<NBLK, 256, SCAN_SMEM>>>(1, out, mask_h);                        // #7
    k_out_tr<<<dim3(512, 32), 256>>>(out);                                      // #8
}

// round 13
// speedup vs baseline: 1.5633x; 1.0150x over previous
#include <cuda_runtime.h>
#include <math.h>

// Problem constants
#define DIRS 2
#define BB   32
#define TT   512
#define DD   512
#define HH   512
#define G4   2048            // 4*H
#define TBM  16384           // T*B
#define NBLK 128             // persistent scan grid (1 block/SM, all co-resident)

static const size_t OUT_HN = (size_t)BB * TT * 2 * HH;   // 16777216
static const size_t OUT_CN = OUT_HN + 4ULL * BB * HH;    // 16842752

typedef unsigned long long ull;

// ---------------- scratch (static device globals; no allocation) ----------------
__device__ __align__(16) float g_xm[(size_t)TBM * 1024];
__device__ __align__(16) float g_xg[(size_t)DIRS * G4 * TBM];          // TRANSPOSED: [dir][gate*512+hc][t*B+b]
__device__ __align__(16) float g_y[(size_t)DIRS * HH * TBM];           // [dir][hc][t][b]
__device__ __align__(16) float g_whhT[(size_t)2 * DIRS * HH * HH * 4]; // [layer][dir][hc][k][gate]
__device__ __align__(16) float g_hmT[2][DIRS * HH * BB];               // ping-pong [par][dir][k][b]
__device__ unsigned g_flags[DIRS * 64 * 32];                           // flag per (dir,jt), 128B apart

// init-barrier state (atomic barrier used once per scan launch)
__device__ unsigned g_bar_count = 0;
__device__ unsigned g_bar_gen = 0;

// ---------------- f32x2 helpers ----------------
__device__ __forceinline__ ull splat2(float x) {
    ull r; unsigned u = __float_as_uint(x);
    asm("mov.b64 %0, {%1, %1};" : "=l"(r) : "r"(u));
    return r;
}
__device__ __forceinline__ ull ffma2(ull a, ull b, ull c) {
    ull d;
    asm("fma.rn.f32x2 %0, %1, %2, %3;" : "=l"(d) : "l"(a), "l"(b), "l"(c));
    return d;
}
__device__ __forceinline__ float lo2(ull v) { return __uint_as_float((unsigned)(v & 0xffffffffu)); }
__device__ __forceinline__ float hi2(ull v) { return __uint_as_float((unsigned)(v >> 32)); }

// NaN-safe fast activations (MUFU-based)
__device__ __forceinline__ float fast_sigmoid(float x) {
    return __fdividef(1.0f, 1.0f + __expf(-x));
}
__device__ __forceinline__ float fast_tanh(float x) {
    return 1.0f - __fdividef(2.0f, 1.0f + __expf(2.0f * x));
}

// acquire/release flag ops (gpu scope)
__device__ __forceinline__ unsigned ld_acq(const unsigned* p) {
    unsigned v;
    asm volatile("ld.acquire.gpu.u32 %0, [%1];" : "=r"(v) : "l"(p) : "memory");
    return v;
}
__device__ __forceinline__ void st_rel(unsigned* p, unsigned v) {
    asm volatile("st.release.gpu.u32 [%0], %1;" :: "l"(p), "r"(v) : "memory");
}

// tf32 round-to-nearest conversion
__device__ __forceinline__ unsigned cvt_tf32(float f) {
    unsigned u;
    asm("cvt.rna.tf32.f32 %0, %1;" : "=r"(u) : "f"(f));
    return u;
}

// m16n8k8 tf32 MMA (row.col): D += A*B
__device__ __forceinline__ void mma_tf32(float* d, const unsigned* a, const unsigned* b) {
    asm volatile(
        "mma.sync.aligned.m16n8k8.row.col.f32.tf32.tf32.f32 "
        "{%0,%1,%2,%3}, {%4,%5,%6,%7}, {%8,%9}, {%0,%1,%2,%3};"
        : "+f"(d[0]), "+f"(d[1]), "+f"(d[2]), "+f"(d[3])
        : "r"(a[0]), "r"(a[1]), "r"(a[2]), "r"(a[3]), "r"(b[0]), "r"(b[1]));
}

// atomic sense-reversing grid barrier: used ONCE per scan launch (init only)
__device__ __forceinline__ void grid_barrier() {
    __syncthreads();
    if (threadIdx.x == 0) {
        __threadfence();
        volatile unsigned* genp = &g_bar_gen;
        unsigned old = *genp;
        unsigned t = atomicAdd(&g_bar_count, 1u);
        if (t == NBLK - 1) {
            g_bar_count = 0;
            __threadfence();
            g_bar_gen = old + 1;
        } else {
            while (*genp == old) {}
        }
        __threadfence();
    }
    __syncthreads();
}

// ---------------- prep kernels ----------------
__global__ void k_mask_in0(const float* __restrict__ x, const float* __restrict__ mask_x) {
    int gid = blockIdx.x * 256 + threadIdx.x;          // < 8388608
    int k = gid & 511; int b = (gid >> 9) & 31; int t = gid >> 14;
    g_xm[gid] = x[((size_t)b * TT + t) * DD + k] * mask_x[b * 512 + k];
}

__global__ void k_build_whhT(const float* __restrict__ w0, const float* __restrict__ w1) {
    int gid = blockIdx.x * 256 + threadIdx.x;          // < 4194304
    int g = gid & 3; int k = (gid >> 2) & 511; int hc = (gid >> 11) & 511;
    int dir = (gid >> 20) & 1; int layer = (gid >> 21) & 1;
    const float* w = layer ? w1 : w0;
    g_whhT[gid] = w[(size_t)dir * G4 * HH + (size_t)(g * HH + hc) * HH + k];
}

// tiled transpose: g_xm[(t*32+b)*1024 + jg] = g_y[jg][t][b] * mask_out[b][jg]
__global__ void k_build_in1(const float* __restrict__ mask_out) {
    __shared__ float tile[32][33];
    const int t = blockIdx.x;          // 0..511
    const int jt = blockIdx.y;         // 0..31
    const int wid = threadIdx.x >> 5, lane = threadIdx.x & 31;
#pragma unroll
    for (int i = 0; i < 4; i++) {
        int r = i * 8 + wid;
        tile[r][lane] = g_y[(size_t)(jt * 32 + r) * TBM + t * 32 + lane];
    }
    __syncthreads();
#pragma unroll
    for (int i = 0; i < 4; i++) {
        int b = i * 8 + wid;
        int jg = jt * 32 + lane;
        g_xm[((size_t)t * 32 + b) * 1024 + jg] = tile[lane][b] * mask_out[b * 1024 + jg];
    }
}

// tiled transpose: out[b][t][jg] = g_y[jg][t][b]   (layer-1 outputs)
__global__ void k_out_tr(float* __restrict__ out) {
    __shared__ float tile[32][33];
    const int t = blockIdx.x;
    const int jt = blockIdx.y;
    const int wid = threadIdx.x >> 5, lane = threadIdx.x & 31;
#pragma unroll
    for (int i = 0; i < 4; i++) {
        int r = i * 8 + wid;
        tile[r][lane] = g_y[(size_t)(jt * 32 + r) * TBM + t * 32 + lane];
    }
    __syncthreads();
#pragma unroll
    for (int i = 0; i < 4; i++) {
        int b = i * 8 + wid;
        out[((size_t)b * TT + t) * 1024 + jt * 32 + lane] = tile[lane][b];
    }
}

// ---------------- tf32 tensor-core input-projection GEMM (TRANSPOSED output) ----------------
// C_T[dir][n][m] = sum_k A[m,k]*W[n,k] + bias[n];  n = gate*512+hc, m = t*B+b.
#define GS 20   // smem floats per row

__global__ void __launch_bounds__(256, 2) gemm_tf32(
    const float* __restrict__ A, const float* __restrict__ Wbase,
    const float* __restrict__ biasbase, float* __restrict__ Cbase, int K)
{
    __shared__ unsigned sA[2][128 * GS];
    __shared__ unsigned sB[2][128 * GS];
    const int dir = blockIdx.z;
    const float* W = Wbase + (size_t)dir * G4 * K;
    const float* bias = biasbase + dir * G4;
    float* C = Cbase + (size_t)dir * G4 * TBM;

    const int tid = threadIdx.x;
    const int m0 = blockIdx.y * 128, n0 = blockIdx.x * 128;
    const int warp = tid >> 5, lane = tid & 31;
    const int wm0 = (warp & 3) * 32;
    const int wn0 = (warp >> 2) * 64;
    const int grp = lane >> 2, tig = lane & 3;

    const int ldr = tid >> 1;
    const int ldh = (tid & 1) * 8;
    const float* Ap = A + (size_t)(m0 + ldr) * K + ldh;
    const float* Wp = W + (size_t)(n0 + ldr) * K + ldh;
    unsigned* stA = &sA[0][ldr * GS + ldh];
    unsigned* stB = &sB[0][ldr * GS + ldh];
    const int bufstep = 128 * GS;

    float acc[2][8][4];
#pragma unroll
    for (int i = 0; i < 2; i++)
#pragma unroll
        for (int j = 0; j < 8; j++)
#pragma unroll
            for (int q = 0; q < 4; q++) acc[i][j][q] = 0.f;

    float bsv[8][2];
#pragma unroll
    for (int nt = 0; nt < 8; nt++) {
        int c = n0 + wn0 + nt * 8 + tig * 2;
        bsv[nt][0] = bias[c]; bsv[nt][1] = bias[c + 1];
    }

    {
        float4 a0 = *(const float4*)(Ap), a1 = *(const float4*)(Ap + 4);
        float4 w0 = *(const float4*)(Wp), w1 = *(const float4*)(Wp + 4);
        stA[0] = cvt_tf32(a0.x); stA[1] = cvt_tf32(a0.y); stA[2] = cvt_tf32(a0.z); stA[3] = cvt_tf32(a0.w);
        stA[4] = cvt_tf32(a1.x); stA[5] = cvt_tf32(a1.y); stA[6] = cvt_tf32(a1.z); stA[7] = cvt_tf32(a1.w);
        stB[0] = cvt_tf32(w0.x); stB[1] = cvt_tf32(w0.y); stB[2] = cvt_tf32(w0.z); stB[3] = cvt_tf32(w0.w);
        stB[4] = cvt_tf32(w1.x); stB[5] = cvt_tf32(w1.y); stB[6] = cvt_tf32(w1.z); stB[7] = cvt_tf32(w1.w);
    }
    __syncthreads();

    const int KT = K >> 4;
    for (int kt = 0; kt < KT; kt++) {
        const int buf = kt & 1;
        float4 na0, na1, nw0, nw1;
        const bool more = (kt + 1 < KT);
        if (more) {
            const float* ap = Ap + (kt + 1) * 16;
            const float* wp = Wp + (kt + 1) * 16;
            na0 = *(const float4*)(ap); na1 = *(const float4*)(ap + 4);
            nw0 = *(const float4*)(wp); nw1 = *(const float4*)(wp + 4);
        }

        const unsigned* bA = &sA[0][buf * bufstep];
        const unsigned* bW = &sB[0][buf * bufstep];
#pragma unroll
        for (int ks = 0; ks < 16; ks += 8) {
            unsigned afr[2][4];
#pragma unroll
            for (int mt = 0; mt < 2; mt++) {
                int ra = wm0 + mt * 16 + grp;
                afr[mt][0] = bA[ra * GS + ks + tig];
                afr[mt][1] = bA[(ra + 8) * GS + ks + tig];
                afr[mt][2] = bA[ra * GS + ks + tig + 4];
                afr[mt][3] = bA[(ra + 8) * GS + ks + tig + 4];
            }
#pragma unroll
            for (int nt = 0; nt < 8; nt++) {
                int rb = wn0 + nt * 8 + grp;
                unsigned bfr[2];
                bfr[0] = bW[rb * GS + ks + tig];
                bfr[1] = bW[rb * GS + ks + tig + 4];
                mma_tf32(acc[0][nt], afr[0], bfr);
                mma_tf32(acc[1][nt], afr[1], bfr);
            }
        }

        if (more) {
            unsigned* dA = stA + (buf ^ 1) * bufstep;
            unsigned* dB = stB + (buf ^ 1) * bufstep;
            dA[0] = cvt_tf32(na0.x); dA[1] = cvt_tf32(na0.y); dA[2] = cvt_tf32(na0.z); dA[3] = cvt_tf32(na0.w);
            dA[4] = cvt_tf32(na1.x); dA[5] = cvt_tf32(na1.y); dA[6] = cvt_tf32(na1.z); dA[7] = cvt_tf32(na1.w);
            dB[0] = cvt_tf32(nw0.x); dB[1] = cvt_tf32(nw0.y); dB[2] = cvt_tf32(nw0.z); dB[3] = cvt_tf32(nw0.w);
            dB[4] = cvt_tf32(nw1.x); dB[5] = cvt_tf32(nw1.y); dB[6] = cvt_tf32(nw1.z); dB[7] = cvt_tf32(nw1.w);
            __syncthreads();
        }
    }

    // TRANSPOSED epilogue: C[n * TBM + m]  (scattered here = coalesced in the scan)
#pragma unroll
    for (int mt = 0; mt < 2; mt++) {
        int r = m0 + wm0 + mt * 16 + grp;
#pragma unroll
        for (int nt = 0; nt < 8; nt++) {
            int c = n0 + wn0 + nt * 8 + tig * 2;
            C[(size_t)c * TBM + r]             = acc[mt][nt][0] + bsv[nt][0];
            C[(size_t)(c + 1) * TBM + r]       = acc[mt][nt][1] + bsv[nt][1];
            C[(size_t)c * TBM + r + 8]         = acc[mt][nt][2] + bsv[nt][0];
            C[(size_t)(c + 1) * TBM + r + 8]   = acc[mt][nt][3] + bsv[nt][1];
        }
    }
}

// ---------------- full-K persistent scan: warp-per-hc, coalesced xg + double prefetch ----------------
// 128 blocks: (dir = bx>>6, jt = bx&63). Warp w = hc jt*8+w; thread lane = b.
// xg reads from transposed g_xg: 4 coalesced 128B lines/warp/step, prefetched one step ahead.
#define SCAN_SMEM (65536 + 65536)   // weights + h stage

__global__ void __launch_bounds__(256, 1) lstm_scan(int layer, float* __restrict__ out,
                                                    const float* __restrict__ mask_h) {
    extern __shared__ __align__(16) char smem[];
    ull* sw = (ull*)smem;                         // [8 hc][512 k][2]  (i,f),(g,o)
    float* sh = (float*)(smem + 65536);           // [512 k][32 b]

    const int bx = blockIdx.x;
    const int tid = threadIdx.x;
    const int dirb = bx >> 6;
    const int jt = bx & 63;
    const int wid = tid >> 5;                     // hc within tile
    const int lane = tid & 31;                    // b
    const int hcg = jt * 8 + wid;

    // load weight slice once
    {
        const float4* whhT4 = (const float4*)g_whhT;
        const size_t base = ((size_t)(layer * 2 + dirb) * 512 + jt * 8) * 512;
        float4* sw4 = (float4*)sw;
        for (int idx = tid; idx < 4096; idx += 256)
            sw4[idx] = whhT4[base + idx];
    }

    const float mh = mask_h[(size_t)layer * 16384 + lane * 512 + hcg];
    float h_r = 0.f, c_r = 0.f;

    // init h(-1) = 0 and reset own flag; one atomic barrier publishes everything
    g_hmT[1][dirb * 16384 + hcg * 32 + lane] = 0.f;
    if (tid == 0) *(volatile unsigned*)&g_flags[(dirb * 64 + jt) * 32] = 0u;
    grid_barrier();

    unsigned* myflag = g_flags + (dirb * 64 + jt) * 32;
    const ull* wrow = sw + (size_t)wid * 1024;    // 512 k * 2 ull
    float* yrow = g_y + ((size_t)dirb * 512 + hcg) * TBM;

    // transposed xg base for this (dir,hc,lane): gate g at + g*512*TBM
    const float* xbase = g_xg + ((size_t)dirb * G4 + hcg) * TBM + lane;
    #define XG_G (512ULL * TBM)

    // prefetch step 0
    int t0 = dirb ? (TT - 1) : 0;
    float xi = __ldcg(xbase + (size_t)t0 * BB);
    float xf = __ldcg(xbase + (size_t)t0 * BB + XG_G);
    float xg_ = __ldcg(xbase + (size_t)t0 * BB + 2 * XG_G);
    float xo = __ldcg(xbase + (size_t)t0 * BB + 3 * XG_G);

    for (int s = 0; s < TT; s++) {
        const int t = dirb ? (TT - 1 - s) : s;

        // prefetch xg for s+1 (coalesced; a full GEMM of slack)
        float nxi = 0.f, nxf = 0.f, nxg = 0.f, nxo = 0.f;
        if (s + 1 < TT) {
            const int tn = dirb ? (TT - 2 - s) : (s + 1);
            const float* p = xbase + (size_t)tn * BB;
            nxi = __ldcg(p);
            nxf = __ldcg(p + XG_G);
            nxg = __ldcg(p + 2 * XG_G);
            nxo = __ldcg(p + 3 * XG_G);
        }

        // wait for the 8 producers of this warp's k-chunk (lanes 0..7 poll, tight spin)
        if (s > 0 && lane < 8) {
            const unsigned* pf = g_flags + (dirb * 64 + wid * 8 + lane) * 32;
            unsigned tgt = (unsigned)s;
            while (ld_acq(pf) < tgt) {}
        }
        __syncwarp();

        // stage own 64-k chunk of h(s-1): 512 float4, 16 per lane, coalesced
        {
            const float4* hb = (const float4*)(g_hmT[(s + 1) & 1]) + dirb * 4096 + wid * 512;
            float4* sh4 = (float4*)sh + wid * 512;
#pragma unroll
            for (int i = 0; i < 16; i++)
                sh4[i * 32 + lane] = __ldcg(hb + i * 32 + lane);
        }
        __syncthreads();   // all chunks staged

        // full-K GEMM: 4 gates for (hcg, b=lane)
        ull aif = 0, ago = 0;
        const float* hcol = sh + lane;
#pragma unroll 8
        for (int k = 0; k < 512; k++) {
            ull wif = wrow[k * 2];
            ull wgo = wrow[k * 2 + 1];
            ull h2 = splat2(hcol[k * 32]);
            aif = ffma2(h2, wif, aif);
            ago = ffma2(h2, wgo, ago);
        }

        // pointwise LSTM in-register
        float gi = lo2(aif) + xi;
        float gf = hi2(aif) + xf;
        float gg = lo2(ago) + xg_;
        float go = hi2(ago) + xo;
        c_r = fast_sigmoid(gf) * c_r + fast_sigmoid(gi) * fast_tanh(gg);
        h_r = fast_sigmoid(go) * fast_tanh(c_r);

        // critical-path store (coalesced 128B/warp), then block-wide release
        __stcg(&g_hmT[s & 1][dirb * 16384 + hcg * 32 + lane], h_r * mh);
        __syncthreads();
        if (tid == 0) st_rel(myflag, (unsigned)(s + 1));

        // off-path coalesced y store
        yrow[(size_t)t * BB + lane] = h_r;

        xi = nxi; xf = nxf; xg_ = nxg; xo = nxo;
    }

    // final hn / cn: [layer*2+dir][b][h]
    out[OUT_HN + (size_t)layer * 32768 + dirb * 16384 + lane * 512 + hcg] = h_r;
    out[OUT_CN + (size_t)layer * 32768 + dirb * 16384 + lane * 512 + hcg] = c_r;
}

// ---------------- launcher ----------------
extern "C" void kernel_launch(void* const* d_in, const int* in_sizes, int n_in,
                              void* d_out, int out_size) {
    (void)in_sizes; (void)n_in; (void)out_size;
    const float* x       = (const float*)d_in[0];
    const float* mask_x  = (const float*)d_in[1];
    const float* mask_out= (const float*)d_in[2];
    const float* mask_h  = (const float*)d_in[3];
    const float* w_ih_l0 = (const float*)d_in[4];
    const float* w_hh_l0 = (const float*)d_in[5];
    const float* b_l0    = (const float*)d_in[6];
    const float* w_ih_l1 = (const float*)d_in[7];
    const float* w_hh_l1 = (const float*)d_in[8];
    const float* b_l1    = (const float*)d_in[9];
    float* out = (float*)d_out;

    float *p_xm = nullptr, *p_xg = nullptr;
    cudaGetSymbolAddress((void**)&p_xm, g_xm);
    cudaGetSymbolAddress((void**)&p_xg, g_xg);

    cudaFuncSetAttribute(lstm_scan, cudaFuncAttributeMaxDynamicSharedMemorySize, SCAN_SMEM);

    // our launches #1..#3 before scan0 (#4) -> process #6 = scan0 under ncu -s 5
    k_mask_in0<<<8388608 / 256, 256>>>(x, mask_x);                              // #1
    gemm_tf32<<<dim3(16, 128, 2), 256>>>(p_xm, w_ih_l0, b_l0, p_xg, DD);        // #2
    k_build_whhT<<<4194304 / 256, 256>>>(w_hh_l0, w_hh_l1);                     // #3

    lstm_scan<<<NBLK, 256, SCAN_SMEM>>>(0, out, mask_h);                        // #4

    k_build_in1<<<dim3(512, 32), 256>>>(mask_out);                              // #5
    gemm_tf32<<<dim3(16, 128, 2), 256>>>(p_xm, w_ih_l1, b_l1, p_xg, 2 * HH);    // #6
    lstm_scan<<<NBLK, 256, SCAN_SMEM>>>(1, out, mask_h);                        // #7
    k_out_tr<<<dim3(512, 32), 256>>>(out);                                      // #8
}